// round 2
// baseline (speedup 1.0000x reference)
#include <cuda_runtime.h>
#include <cstdint>

// Elementwise: out = (x+2) + 3x - (x-1)*(x/2)  ==  -0.5*x^2 + 4.5*x + 2
// N = 8192*16384 = 134217728 -> n_vec = 33554432 float4, divisible by
// (BLOCKS*THREADS*UNROLL) = 2048*256*4 = 2097152 exactly (16 iterations),
// so the main loop needs no bounds checks; keep a guarded tail for safety.

#define THREADS 256
#define BLOCKS  2048
#define UNROLL  4

__global__ __launch_bounds__(THREADS) void fused_elem_kernel(
    const float4* __restrict__ x, float4* __restrict__ out, int n_vec)
{
    const int tid = blockIdx.x * THREADS + threadIdx.x;
    const int stride = BLOCKS * THREADS;                  // threads in grid
    const int chunk = stride * UNROLL;                    // vectors per loop iter

    int base = tid;
    // Main loop: front-batch UNROLL independent LDG.128s (MLP=4/warp slot)
    for (; base + (UNROLL - 1) * stride < n_vec; base += chunk) {
        float4 v[UNROLL];
#pragma unroll
        for (int k = 0; k < UNROLL; k++)
            v[k] = __ldcs(&x[base + k * stride]);
#pragma unroll
        for (int k = 0; k < UNROLL; k++) {
            float4 r;
            r.x = fmaf(v[k].x, fmaf(v[k].x, -0.5f, 4.5f), 2.0f);
            r.y = fmaf(v[k].y, fmaf(v[k].y, -0.5f, 4.5f), 2.0f);
            r.z = fmaf(v[k].z, fmaf(v[k].z, -0.5f, 4.5f), 2.0f);
            r.w = fmaf(v[k].w, fmaf(v[k].w, -0.5f, 4.5f), 2.0f);
            __stcs(&out[base + k * stride], r);
        }
    }
    // Tail (not taken for this problem's N, but keeps kernel general)
    for (; base < n_vec; base += stride) {
        float4 v = __ldcs(&x[base]);
        float4 r;
        r.x = fmaf(v.x, fmaf(v.x, -0.5f, 4.5f), 2.0f);
        r.y = fmaf(v.y, fmaf(v.y, -0.5f, 4.5f), 2.0f);
        r.z = fmaf(v.z, fmaf(v.z, -0.5f, 4.5f), 2.0f);
        r.w = fmaf(v.w, fmaf(v.w, -0.5f, 4.5f), 2.0f);
        __stcs(&out[base], r);
    }
}

extern "C" void kernel_launch(void* const* d_in, const int* in_sizes, int n_in,
                              void* d_out, int out_size) {
    const float* x = (const float*)d_in[0];
    float* out = (float*)d_out;
    int n = in_sizes[0];     // 134217728
    int n_vec = n >> 2;      // 33554432

    fused_elem_kernel<<<BLOCKS, THREADS>>>((const float4*)x, (float4*)out, n_vec);
}

// round 4
// speedup vs baseline: 1.0546x; 1.0546x over previous
#include <cuda_runtime.h>
#include <cstdint>

// Elementwise: out = (x+2) + 3x - (x-1)*(x/2)  ==  -0.5*x^2 + 4.5*x + 2
// N = 8192*16384 = 134217728 -> n_vec = 33554432 float4.
// Flat launch, each thread handles 2 float4s split across the two halves:
//   i  and  i + n_vec/2.
// half = 16777216 = 65536 blocks * 256 threads exactly -> no guard, no tail.

#define THREADS 256

__global__ __launch_bounds__(THREADS) void fused_elem_kernel(
    const float4* __restrict__ x, float4* __restrict__ out, int half)
{
    const int i = blockIdx.x * THREADS + threadIdx.x;
    const int j = i + half;

    // Front-batch both independent loads (MLP=2, zero loop state)
    float4 a = __ldcs(&x[i]);
    float4 b = __ldcs(&x[j]);

    float4 ra, rb;
    ra.x = fmaf(a.x, fmaf(a.x, -0.5f, 4.5f), 2.0f);
    ra.y = fmaf(a.y, fmaf(a.y, -0.5f, 4.5f), 2.0f);
    ra.z = fmaf(a.z, fmaf(a.z, -0.5f, 4.5f), 2.0f);
    ra.w = fmaf(a.w, fmaf(a.w, -0.5f, 4.5f), 2.0f);
    __stcs(&out[i], ra);

    rb.x = fmaf(b.x, fmaf(b.x, -0.5f, 4.5f), 2.0f);
    rb.y = fmaf(b.y, fmaf(b.y, -0.5f, 4.5f), 2.0f);
    rb.z = fmaf(b.z, fmaf(b.z, -0.5f, 4.5f), 2.0f);
    rb.w = fmaf(b.w, fmaf(b.w, -0.5f, 4.5f), 2.0f);
    __stcs(&out[j], rb);
}

extern "C" void kernel_launch(void* const* d_in, const int* in_sizes, int n_in,
                              void* d_out, int out_size) {
    const float* x = (const float*)d_in[0];
    float* out = (float*)d_out;
    int n = in_sizes[0];       // 134217728
    int n_vec = n >> 2;        // 33554432
    int half = n_vec >> 1;     // 16777216

    int blocks = half / THREADS;   // 65536, exact
    fused_elem_kernel<<<blocks, THREADS>>>((const float4*)x, (float4*)out, half);
}